// round 13
// baseline (speedup 1.0000x reference)
#include <cuda_runtime.h>
#include <cstdint>

#define S_LEN 2048
#define B_SZ  32
#define I_DIM 256
#define H_DIM 512

#define NCLUSTERS    16
#define CRANKS       8
#define ROWS_PER_CTA 64
#define REC_THREADS  512

// ---------------- PTX helpers ----------------
__device__ __forceinline__ uint32_t smem_u32(const void* p) {
    uint32_t a;
    asm("{ .reg .u64 t; cvta.to.shared.u64 t, %1; cvt.u32.u64 %0, t; }" : "=r"(a) : "l"(p));
    return a;
}
__device__ __forceinline__ uint32_t mapa_cluster(uint32_t addr, uint32_t rank) {
    uint32_t r;
    asm("mapa.shared::cluster.u32 %0, %1, %2;" : "=r"(r) : "r"(addr), "r"(rank));
    return r;
}
__device__ __forceinline__ void mbar_init(uint32_t mbar, uint32_t cnt) {
    asm volatile("mbarrier.init.shared.b64 [%0], %1;" :: "r"(mbar), "r"(cnt) : "memory");
}
__device__ __forceinline__ void mbar_expect_tx(uint32_t mbar, uint32_t bytes) {
    asm volatile("mbarrier.arrive.expect_tx.shared.b64 _, [%0], %1;" :: "r"(mbar), "r"(bytes) : "memory");
}
__device__ __forceinline__ void mbar_wait(uint32_t mbar, uint32_t phase) {
    uint32_t done = 0;
    while (!done) {
        asm volatile(
            "{\n\t.reg .pred p;\n\t"
            "mbarrier.try_wait.parity.acquire.cluster.shared::cta.b64 p, [%1], %2, 0x989680;\n\t"
            "selp.b32 %0, 1, 0, p;\n\t}"
            : "=r"(done) : "r"(mbar), "r"(phase) : "memory");
    }
}
// bulk DSMEM copy: local shared -> peer shared, complete_tx at peer mbar
__device__ __forceinline__ void bulk_copy_cluster(uint32_t dst, uint32_t src,
                                                  uint32_t bytes, uint32_t peer_mbar) {
    asm volatile(
        "cp.async.bulk.shared::cluster.shared::cta.mbarrier::complete_tx::bytes [%0], [%1], %2, [%3];"
        :: "r"(dst), "r"(src), "r"(bytes), "r"(peer_mbar) : "memory");
}
__device__ __forceinline__ void fence_proxy_async_cta() {
    asm volatile("fence.proxy.async.shared::cta;" ::: "memory");
}
__device__ __forceinline__ unsigned long long ffma2(unsigned long long a, unsigned long long b,
                                                    unsigned long long c) {
    unsigned long long d;
    asm("fma.rn.f32x2 %0, %1, %2, %3;" : "=l"(d) : "l"(a), "l"(b), "l"(c));
    return d;
}
__device__ __forceinline__ unsigned long long add2(unsigned long long a, unsigned long long b) {
    unsigned long long d;
    asm("add.rn.f32x2 %0, %1, %2;" : "=l"(d) : "l"(a), "l"(b));
    return d;
}
__device__ __forceinline__ float fold2(unsigned long long v) {
    union { unsigned long long u; float2 f; } c; c.u = v;
    return c.f.x + c.f.y;
}
__device__ __forceinline__ unsigned long long pack2(float x, float y) {
    unsigned long long r;
    asm("mov.b64 %0, {%1, %2};" : "=l"(r) : "r"(__float_as_uint(x)), "r"(__float_as_uint(y)));
    return r;
}
__device__ __forceinline__ float2 unpack2(unsigned long long v) {
    union { unsigned long long u; float2 f; } c; c.u = v;
    return c.f;
}
__device__ __forceinline__ float fast_tanh(float h) {
    float hc = fminf(fmaxf(h, -15.f), 15.f);
    float e2 = __expf(2.f * hc);
    return __fdividef(e2 - 1.f, e2 + 1.f);
}
__device__ __forceinline__ void cluster_sync() {
    asm volatile("barrier.cluster.arrive.aligned;\n\tbarrier.cluster.wait.aligned;" ::: "memory");
}

// ---------------- xproj GEMM (R3-proven): out[m,n] = sum_k x[m,k] * Wx[n,k] ----------------
#define BM 128
#define BN 128
#define BK 16

__global__ void __launch_bounds__(256, 2)
xproj_kernel(const float* __restrict__ x,
             const float* __restrict__ Wx,
             float* __restrict__ out)
{
    __shared__ float As[BK][BM];
    __shared__ float Bs[BK][BN];
    const int tid = threadIdx.x;
    const int m0 = blockIdx.y * BM;
    const int n0 = blockIdx.x * BN;
    const int tx = tid & 15;
    const int ty = tid >> 4;

    float acc[8][8];
#pragma unroll
    for (int i = 0; i < 8; i++)
#pragma unroll
        for (int j = 0; j < 8; j++) acc[i][j] = 0.f;

    const float* Aptr = x  + (size_t)m0 * I_DIM;
    const float* Bptr = Wx + (size_t)n0 * I_DIM;

    for (int k0 = 0; k0 < I_DIM; k0 += BK) {
#pragma unroll
        for (int l = 0; l < 2; l++) {
            int idx = tid + l * 256;
            int r   = idx >> 2;
            int c4  = (idx & 3) * 4;
            float4 a = *(const float4*)(Aptr + (size_t)r * I_DIM + k0 + c4);
            As[c4 + 0][r] = a.x; As[c4 + 1][r] = a.y;
            As[c4 + 2][r] = a.z; As[c4 + 3][r] = a.w;
            float4 b = *(const float4*)(Bptr + (size_t)r * I_DIM + k0 + c4);
            Bs[c4 + 0][r] = b.x; Bs[c4 + 1][r] = b.y;
            Bs[c4 + 2][r] = b.z; Bs[c4 + 3][r] = b.w;
        }
        __syncthreads();
#pragma unroll
        for (int kk = 0; kk < BK; kk++) {
            float ra[8], rb[8];
            float4 ra0 = *(const float4*)&As[kk][ty * 8];
            float4 ra1 = *(const float4*)&As[kk][ty * 8 + 4];
            ra[0]=ra0.x; ra[1]=ra0.y; ra[2]=ra0.z; ra[3]=ra0.w;
            ra[4]=ra1.x; ra[5]=ra1.y; ra[6]=ra1.z; ra[7]=ra1.w;
            float4 rb0 = *(const float4*)&Bs[kk][tx * 8];
            float4 rb1 = *(const float4*)&Bs[kk][tx * 8 + 4];
            rb[0]=rb0.x; rb[1]=rb0.y; rb[2]=rb0.z; rb[3]=rb0.w;
            rb[4]=rb1.x; rb[5]=rb1.y; rb[6]=rb1.z; rb[7]=rb1.w;
#pragma unroll
            for (int i = 0; i < 8; i++)
#pragma unroll
                for (int j = 0; j < 8; j++)
                    acc[i][j] += ra[i] * rb[j];
        }
        __syncthreads();
    }

#pragma unroll
    for (int i = 0; i < 8; i++) {
        float* o = out + (size_t)(m0 + ty * 8 + i) * H_DIM + n0 + tx * 8;
        *(float4*)o       = make_float4(acc[i][0], acc[i][1], acc[i][2], acc[i][3]);
        *(float4*)(o + 4) = make_float4(acc[i][4], acc[i][5], acc[i][6], acc[i][7]);
    }
}

// ---------------- recurrence (staggered batches + bulk DSMEM exchange) ----------------
// 16 clusters x 8 CTAs; cluster c: batches (2c, 2c+1). CTA rank r: rows
// [r*64, r*64+64), Wh in registers (f32x2). Step = 2 phases. Phase bb:
// wait mbar[P][bb] -> broadcast-LDS FFMA2 half-GEMV -> partials[P][bb] ->
// named bar (arrive for 15 warps) -> ONE-warp tail (warp bb): packed f32x2
// reduce/update, 2 tanh, STS 256B stage[P^1][bb], syncwarp, lanes 0-7:
// fence + cp.async.bulk 256B to each peer's th[P^1][bb][rank*64..] with
// complete_tx at peer mbar[P^1][bb] (expect 2048B = 8 sources). Zero
// per-message ingress; DMA latency hidden by the other batch's phase.
struct RecSmem {
    float th[2][2][H_DIM];        // [parity][batch][k]       8KB (copy dest)
    float part[2][2][16][64];     // [parity][batch][w][row] 32KB
    float stage[2][2][64];        // [tgt parity][batch][row] 1KB (copy src)
    unsigned long long mbar[4];   // [parity*2 + batch]
};

__global__ void __cluster_dims__(CRANKS, 1, 1) __launch_bounds__(REC_THREADS, 1)
rec_kernel(const float* __restrict__ Wh,
           const float* __restrict__ tau,
           const float* __restrict__ bias,
           float* __restrict__ out)
{
    __shared__ __align__(16) RecSmem sm;

    const int cid  = blockIdx.x / CRANKS;
    const int rank = blockIdx.x % CRANKS;
    const int t    = threadIdx.x;
    const int jp   = t & 31;
    const int kb   = t >> 5;
    const int j0   = 2 * jp;

    // Wh slice in registers (rows j0, j0+1; k in [kb*32, kb*32+32))
    unsigned long long wp0[16], wp1[16];
    {
        const ulonglong2* r0 = (const ulonglong2*)(Wh + (size_t)(rank * ROWS_PER_CTA + j0)     * H_DIM + kb * 32);
        const ulonglong2* r1 = (const ulonglong2*)(Wh + (size_t)(rank * ROWS_PER_CTA + j0 + 1) * H_DIM + kb * 32);
#pragma unroll
        for (int i = 0; i < 8; i++) {
            ulonglong2 a = r0[i]; wp0[2*i] = a.x; wp0[2*i+1] = a.y;
            ulonglong2 b = r1[i]; wp1[2*i] = b.x; wp1[2*i+1] = b.y;
        }
    }

    const uint32_t th_base    = smem_u32(&sm.th[0][0][0]);
    const uint32_t stage_base = smem_u32(&sm.stage[0][0][0]);
    const uint32_t mbar_base  = smem_u32(&sm.mbar[0]);
    const uint32_t mbar_rel   = mbar_base - th_base;

    uint32_t peer_th[CRANKS];
#pragma unroll
    for (int r = 0; r < CRANKS; r++) peer_th[r] = mapa_cluster(th_base, r);

    if (t < 4) {
        mbar_init(mbar_base + t * 8, 1);
        mbar_expect_tx(mbar_base + t * 8, 2048);
    }
    __syncthreads();
    cluster_sync();   // peers' mbars live before any bulk copy

    // ---- tail state: warps 0 (batch 0) and 1 (batch 1); lane jj owns rows 2jj,2jj+1 ----
    const int bb  = t >> 5;           // == kb; valid as batch id for t<64
    const int jj  = t & 31;
    const int hg0 = rank * ROWS_PER_CTA + 2 * jj;
    float* outp = out + (size_t)(cid * 2 + bb) * S_LEN * H_DIM + hg0;

    unsigned long long invt2 = 0, A2 = 0, c02 = 0, pre2 = 0, h2 = 0;
    if (t < 64) {
        float2 tt = *(const float2*)(tau + hg0);
        float2 bs = *(const float2*)(bias + hg0);
        float ix = 1.0f / tt.x, iy = 1.0f / tt.y;
        invt2 = pack2(ix, iy);
        A2    = pack2(1.0f - ix, 1.0f - iy);
        c02   = pack2(bs.x * ix, bs.y * iy);
    }

    // ---- step 0: v = 0, h = xp/tau + bias/tau; copy th into parity-1 ----
    if (t < 64) {
        float2 xp = *(const float2*)outp;
        pre2 = ffma2(pack2(xp.x, xp.y), invt2, c02);
        h2 = pre2;
        float2 hf = unpack2(h2);
        unsigned long long pk = pack2(fast_tanh(hf.x), fast_tanh(hf.y));
        *(unsigned long long*)&sm.stage[1][bb][2 * jj] = pk;
        __syncwarp();
        if (jj < 8) {
            fence_proxy_async_cta();
            bulk_copy_cluster(peer_th[jj] + (uint32_t)(2 + bb) * 2048u + (uint32_t)rank * 256u,
                              stage_base + (uint32_t)(2 + bb) * 256u,
                              256u,
                              peer_th[jj] + mbar_rel + (uint32_t)(2 + bb) * 8u);
        }
        *(float2*)outp = hf;
        float2 xn0 = *(const float2*)(outp + H_DIM);
        pre2 = ffma2(pack2(xn0.x, xn0.y), invt2, c02);
    }

    uint32_t ph00 = 0, ph01 = 0, ph10 = 0, ph11 = 0;

#define PHASE_BODY(STEP, P, BB, PH, BARID, LAST)                                   \
    {                                                                              \
        mbar_wait(mbar_base + ((P) * 2 + (BB)) * 8u, (PH));                        \
        if (t == 480) mbar_expect_tx(mbar_base + ((P) * 2 + (BB)) * 8u, 2048);     \
        const ulonglong2* tc = (const ulonglong2*)&sm.th[(P)][(BB)][kb * 32];      \
        unsigned long long a0e = 0ull, a0o = 0ull, a1e = 0ull, a1o = 0ull;         \
        _Pragma("unroll")                                                          \
        for (int i = 0; i < 8; i++) {                                              \
            ulonglong2 U = tc[i];                                                  \
            a0e = ffma2(wp0[2*i],   U.x, a0e);                                     \
            a0o = ffma2(wp0[2*i+1], U.y, a0o);                                     \
            a1e = ffma2(wp1[2*i],   U.x, a1e);                                     \
            a1o = ffma2(wp1[2*i+1], U.y, a1o);                                     \
        }                                                                          \
        *(float2*)&sm.part[(P)][(BB)][kb][j0] =                                    \
            make_float2(fold2(a0e) + fold2(a0o), fold2(a1e) + fold2(a1o));         \
        if (kb == (BB)) {                                                          \
            asm volatile("bar.sync %0, 512;" :: "r"(BARID) : "memory");            \
            const int roff = 2 * jj;                                               \
            unsigned long long s0 = *(const unsigned long long*)&sm.part[(P)][(BB)][0][roff]; \
            unsigned long long s1 = *(const unsigned long long*)&sm.part[(P)][(BB)][1][roff]; \
            unsigned long long s2 = *(const unsigned long long*)&sm.part[(P)][(BB)][2][roff]; \
            unsigned long long s3 = *(const unsigned long long*)&sm.part[(P)][(BB)][3][roff]; \
            _Pragma("unroll")                                                      \
            for (int w = 4; w < 16; w += 4) {                                      \
                s0 = add2(s0, *(const unsigned long long*)&sm.part[(P)][(BB)][w][roff]);     \
                s1 = add2(s1, *(const unsigned long long*)&sm.part[(P)][(BB)][w + 1][roff]); \
                s2 = add2(s2, *(const unsigned long long*)&sm.part[(P)][(BB)][w + 2][roff]); \
                s3 = add2(s3, *(const unsigned long long*)&sm.part[(P)][(BB)][w + 3][roff]); \
            }                                                                      \
            unsigned long long v2 = add2(add2(s0, s1), add2(s2, s3));              \
            h2 = ffma2(h2, A2, ffma2(v2, invt2, pre2));                            \
            float2 hf = unpack2(h2);                                               \
            if (!(LAST)) {                                                         \
                unsigned long long pk = pack2(fast_tanh(hf.x), fast_tanh(hf.y));   \
                *(unsigned long long*)&sm.stage[(P) ^ 1][(BB)][roff] = pk;         \
                __syncwarp();                                                      \
                if (jj < 8) {                                                      \
                    fence_proxy_async_cta();                                       \
                    bulk_copy_cluster(                                             \
                        peer_th[jj] + (uint32_t)((((P) ^ 1) * 2 + (BB)) * 2048) + (uint32_t)rank * 256u, \
                        stage_base + (uint32_t)((((P) ^ 1) * 2 + (BB)) * 256),     \
                        256u,                                                      \
                        peer_th[jj] + mbar_rel + (uint32_t)((((P) ^ 1) * 2 + (BB)) * 8)); \
                }                                                                  \
            }                                                                      \
            *(float2*)(outp + (size_t)(STEP) * H_DIM) = hf;                        \
            pre2 = ffma2(pack2(xn_.x, xn_.y), invt2, c02);                         \
        } else {                                                                   \
            asm volatile("bar.arrive %0, 512;" :: "r"(BARID) : "memory");          \
        }                                                                          \
        (PH) ^= 1;                                                                 \
    }

#define STEP_BODY(STEP, P, PHB0, PHB1, LAST)                                       \
    {                                                                              \
        float2 xn_ = make_float2(0.f, 0.f);                                        \
        if (t < 64 && !(LAST))                                                     \
            xn_ = *(const float2*)(outp + (size_t)((STEP) + 1) * H_DIM);           \
        PHASE_BODY(STEP, P, 0, PHB0, 1, LAST)                                      \
        PHASE_BODY(STEP, P, 1, PHB1, 2, LAST)                                      \
    }

    for (int s = 1; s < S_LEN - 1; s += 2) {
        STEP_BODY(s,     1, ph10, ph11, 0)
        STEP_BODY(s + 1, 0, ph00, ph01, 0)
    }
    STEP_BODY(S_LEN - 1, 1, ph10, ph11, 1)
#undef STEP_BODY
#undef PHASE_BODY

    cluster_sync();   // no CTA exits while peers' copies may target its smem
}

extern "C" void kernel_launch(void* const* d_in, const int* in_sizes, int n_in,
                              void* d_out, int out_size)
{
    const float* x    = (const float*)d_in[0];
    const float* Wx   = (const float*)d_in[1];
    const float* Wh   = (const float*)d_in[2];
    const float* tau  = (const float*)d_in[3];
    const float* bias = (const float*)d_in[4];
    float* out = (float*)d_out;

    dim3 g1(H_DIM / BN, (B_SZ * S_LEN) / BM);
    xproj_kernel<<<g1, 256>>>(x, Wx, out);

    rec_kernel<<<NCLUSTERS * CRANKS, REC_THREADS>>>(Wh, tau, bias, out);
}

// round 14
// speedup vs baseline: 1.4037x; 1.4037x over previous
#include <cuda_runtime.h>
#include <cstdint>

#define S_LEN 2048
#define B_SZ  32
#define I_DIM 256
#define H_DIM 512

#define NCLUSTERS    16
#define CRANKS       8
#define ROWS_PER_CTA 64
#define REC_THREADS  512

// ---------------- PTX helpers ----------------
__device__ __forceinline__ uint32_t smem_u32(const void* p) {
    uint32_t a;
    asm("{ .reg .u64 t; cvta.to.shared.u64 t, %1; cvt.u32.u64 %0, t; }" : "=r"(a) : "l"(p));
    return a;
}
__device__ __forceinline__ uint32_t mapa_cluster(uint32_t addr, uint32_t rank) {
    uint32_t r;
    asm("mapa.shared::cluster.u32 %0, %1, %2;" : "=r"(r) : "r"(addr), "r"(rank));
    return r;
}
__device__ __forceinline__ void mbar_init(uint32_t mbar, uint32_t cnt) {
    asm volatile("mbarrier.init.shared.b64 [%0], %1;" :: "r"(mbar), "r"(cnt) : "memory");
}
__device__ __forceinline__ void mbar_expect_tx(uint32_t mbar, uint32_t bytes) {
    asm volatile("mbarrier.arrive.expect_tx.shared.b64 _, [%0], %1;" :: "r"(mbar), "r"(bytes) : "memory");
}
__device__ __forceinline__ void mbar_arrive_release(uint32_t mbar) {
    asm volatile("mbarrier.arrive.release.cta.shared::cta.b64 _, [%0];" :: "r"(mbar) : "memory");
}
__device__ __forceinline__ void mbar_wait(uint32_t mbar, uint32_t phase) {
    uint32_t done = 0;
    while (!done) {
        asm volatile(
            "{\n\t.reg .pred p;\n\t"
            "mbarrier.try_wait.parity.acquire.cluster.shared::cta.b64 p, [%1], %2, 0x989680;\n\t"
            "selp.b32 %0, 1, 0, p;\n\t}"
            : "=r"(done) : "r"(mbar), "r"(phase) : "memory");
    }
}
__device__ __forceinline__ void st_async_b64(uint32_t daddr, unsigned long long v, uint32_t mbar) {
    asm volatile("st.async.shared::cluster.mbarrier::complete_tx::bytes.b64 [%0], %1, [%2];"
                 :: "r"(daddr), "l"(v), "r"(mbar) : "memory");
}
__device__ __forceinline__ void sts_b64(uint32_t addr, unsigned long long v) {
    asm volatile("st.shared.b64 [%0], %1;" :: "r"(addr), "l"(v) : "memory");
}
__device__ __forceinline__ unsigned long long ffma2(unsigned long long a, unsigned long long b,
                                                    unsigned long long c) {
    unsigned long long d;
    asm("fma.rn.f32x2 %0, %1, %2, %3;" : "=l"(d) : "l"(a), "l"(b), "l"(c));
    return d;
}
__device__ __forceinline__ float fold2(unsigned long long v) {
    union { unsigned long long u; float2 f; } c; c.u = v;
    return c.f.x + c.f.y;
}
__device__ __forceinline__ unsigned long long pack2(float x, float y) {
    unsigned long long r;
    asm("mov.b64 %0, {%1, %2};" : "=l"(r) : "r"(__float_as_uint(x)), "r"(__float_as_uint(y)));
    return r;
}
__device__ __forceinline__ float fast_tanh(float h) {
    float hc = fminf(fmaxf(h, -15.f), 15.f);
    float e2 = __expf(2.f * hc);
    return __fdividef(e2 - 1.f, e2 + 1.f);
}
__device__ __forceinline__ void cluster_sync() {
    asm volatile("barrier.cluster.arrive.aligned;\n\tbarrier.cluster.wait.aligned;" ::: "memory");
}

// ---------------- xproj GEMM (f32x2, verified in R5): out[m,n] = sum_k x[m,k]*Wx[n,k] ----
#define BM 128
#define BN 128
#define BK 16

__global__ void __launch_bounds__(256, 2)
xproj_kernel(const float* __restrict__ x,
             const float* __restrict__ Wx,
             float* __restrict__ out)
{
    __shared__ float As[BK][BM];
    __shared__ float Bs[BK][BN];
    const int tid = threadIdx.x;
    const int m0 = blockIdx.y * BM;
    const int n0 = blockIdx.x * BN;
    const int tx = tid & 15;
    const int ty = tid >> 4;

    unsigned long long acc[8][4];   // [i][jpair], lo = col 2j, hi = col 2j+1
#pragma unroll
    for (int i = 0; i < 8; i++)
#pragma unroll
        for (int j = 0; j < 4; j++) acc[i][j] = 0ull;

    const float* Aptr = x  + (size_t)m0 * I_DIM;
    const float* Bptr = Wx + (size_t)n0 * I_DIM;

    for (int k0 = 0; k0 < I_DIM; k0 += BK) {
#pragma unroll
        for (int l = 0; l < 2; l++) {
            int idx = tid + l * 256;
            int r   = idx >> 2;
            int c4  = (idx & 3) * 4;
            float4 a = *(const float4*)(Aptr + (size_t)r * I_DIM + k0 + c4);
            As[c4 + 0][r] = a.x; As[c4 + 1][r] = a.y;
            As[c4 + 2][r] = a.z; As[c4 + 3][r] = a.w;
            float4 b = *(const float4*)(Bptr + (size_t)r * I_DIM + k0 + c4);
            Bs[c4 + 0][r] = b.x; Bs[c4 + 1][r] = b.y;
            Bs[c4 + 2][r] = b.z; Bs[c4 + 3][r] = b.w;
        }
        __syncthreads();
#pragma unroll
        for (int kk = 0; kk < BK; kk++) {
            float4 ra0 = *(const float4*)&As[kk][ty * 8];
            float4 ra1 = *(const float4*)&As[kk][ty * 8 + 4];
            float ra[8] = {ra0.x, ra0.y, ra0.z, ra0.w, ra1.x, ra1.y, ra1.z, ra1.w};
            const ulonglong2* rbp = (const ulonglong2*)&Bs[kk][tx * 8];
            ulonglong2 rb01 = rbp[0];
            ulonglong2 rb23 = rbp[1];
#pragma unroll
            for (int i = 0; i < 8; i++) {
                unsigned long long rai = pack2(ra[i], ra[i]);
                acc[i][0] = ffma2(rai, rb01.x, acc[i][0]);
                acc[i][1] = ffma2(rai, rb01.y, acc[i][1]);
                acc[i][2] = ffma2(rai, rb23.x, acc[i][2]);
                acc[i][3] = ffma2(rai, rb23.y, acc[i][3]);
            }
        }
        __syncthreads();
    }

#pragma unroll
    for (int i = 0; i < 8; i++) {
        float* o = out + (size_t)(m0 + ty * 8 + i) * H_DIM + n0 + tx * 8;
        union { unsigned long long u; float2 f; } c0, c1, c2, c3;
        c0.u = acc[i][0]; c1.u = acc[i][1]; c2.u = acc[i][2]; c3.u = acc[i][3];
        *(float4*)o       = make_float4(c0.f.x, c0.f.y, c1.f.x, c1.f.y);
        *(float4*)(o + 4) = make_float4(c2.f.x, c2.f.y, c3.f.x, c3.f.y);
    }
}

// ---------------- recurrence (R7 champion + self-send elimination) ----------------
// 16 clusters x 8 CTAs; cluster c: batches (2c, 2c+1). CTA rank r: rows
// [r*64, r*64+64), Wh in registers (f32x2). Per step: mbar wait ->
// broadcast-LDS FFMA2 GEMV -> cf partials -> __syncthreads -> tail t<128:
// reduce part[w][t], 2-FMA update (pre precomputed at prefetch), tanh,
// pair shfl. Pair's pk lands locally via STS.64 + mbarrier.arrive.release
// (even lane), and remotely via st.async.b64 to the 7 OTHER peers (even
// lane covers peers 0-3 minus self, odd covers 4-7 minus self).
// mbar: count 65 (64 even-lane arrives + 1 expect_tx arrive), tx 3584B.
struct RecSmem {
    float th[2][2][H_DIM];     // [buf][batch][k]  8KB  (st.async / STS dest)
    float part[16][128];       // partials, column = owner tid
    unsigned long long mbar[2];
};

__global__ void __cluster_dims__(CRANKS, 1, 1) __launch_bounds__(REC_THREADS, 1)
rec_kernel(const float* __restrict__ Wh,
           const float* __restrict__ tau,
           const float* __restrict__ bias,
           float* __restrict__ out)
{
    __shared__ __align__(16) RecSmem sm;

    const int cid  = blockIdx.x / CRANKS;
    const int rank = blockIdx.x % CRANKS;
    const int t    = threadIdx.x;
    const int jp   = t & 31;
    const int kb   = t >> 5;
    const int j0   = 2 * jp;

    // Wh slice in registers (rows j0, j0+1; k in [kb*32, kb*32+32))
    unsigned long long wp0[16], wp1[16];
    {
        const ulonglong2* r0 = (const ulonglong2*)(Wh + (size_t)(rank * ROWS_PER_CTA + j0)     * H_DIM + kb * 32);
        const ulonglong2* r1 = (const ulonglong2*)(Wh + (size_t)(rank * ROWS_PER_CTA + j0 + 1) * H_DIM + kb * 32);
#pragma unroll
        for (int i = 0; i < 8; i++) {
            ulonglong2 a = r0[i]; wp0[2*i] = a.x; wp0[2*i+1] = a.y;
            ulonglong2 b = r1[i]; wp1[2*i] = b.x; wp1[2*i+1] = b.y;
        }
    }

    const uint32_t th_base   = smem_u32(&sm.th[0][0][0]);
    const uint32_t mbar_base = smem_u32(&sm.mbar[0]);
    const uint32_t mbar_rel  = mbar_base - th_base;

    uint32_t peer_th[CRANKS];
#pragma unroll
    for (int r = 0; r < CRANKS; r++) peer_th[r] = mapa_cluster(th_base, r);

    if (t == 0) {
        mbar_init(mbar_base,     65);  mbar_expect_tx(mbar_base,     3584);
        mbar_init(mbar_base + 8, 65);  mbar_expect_tx(mbar_base + 8, 3584);
    }
    __syncthreads();
    cluster_sync();   // peers' mbars live before any st.async

    // tail state (t < 128): one (batch, row) output per thread
    const int bb = t >> 6;
    const int j  = t & 63;
    const int hg = rank * ROWS_PER_CTA + j;
    const int b  = cid * 2 + bb;
    float* outp = out + (size_t)b * S_LEN * H_DIM + hg;

    float h = 0.f, inv_tau = 1.f, Acoef = 0.f, c0 = 0.f, pre = 0.f;
    if (t < 128) {
        inv_tau = 1.0f / tau[hg];
        Acoef   = 1.0f - inv_tau;
        c0      = bias[hg] * inv_tau;
    }
    // b64 destination offset: even-row base of this thread's pair
    const uint32_t send_off = (uint32_t)(bb * H_DIM + (hg & ~1)) * 4u;
    const int peer0 = (t & 1) * 4;   // even lane: peers 0-3, odd: peers 4-7

    // ---- step 0: v = 0, h = xp/tau + bias/tau ----
    if (t < 128) {
        float xp = outp[0];
        pre = fmaf(xp, inv_tau, c0);
        h = pre;
        float thv = fast_tanh(h);
        float tho = __shfl_xor_sync(0xffffffffu, thv, 1);
        float ho  = __shfl_xor_sync(0xffffffffu, h,   1);
        if (!(t & 1)) *(float2*)outp = make_float2(h, ho);
        unsigned long long pk = (t & 1) ? pack2(tho, thv) : pack2(thv, tho);
        uint32_t d = 4096u + send_off;                       // parity-1 buffer
        uint32_t m = mbar_rel + 8u;
        if (!(t & 1)) sts_b64(th_base + d, pk);              // self via STS
#pragma unroll
        for (int rr = 0; rr < 4; rr++) {
            int pr = peer0 + rr;
            if (pr != rank)
                st_async_b64(peer_th[pr] + d, pk, peer_th[pr] + m);
        }
        if (!(t & 1)) mbar_arrive_release(mbar_base + 8u);
        float xn = outp[(size_t)1 * H_DIM];                  // prefetch step 1
        pre = fmaf(xn, inv_tau, c0);
    }

    uint32_t ph0 = 0, ph1 = 0;

#define STEP_BODY(STEP, P, PH, LAST)                                               \
    {                                                                              \
        float xn = 0.f;                                                            \
        if (t < 128 && !(LAST)) xn = outp[(size_t)((STEP) + 1) * H_DIM];           \
        mbar_wait(mbar_base + (P) * 8, (PH));                                      \
        if (t == 480) mbar_expect_tx(mbar_base + (P) * 8, 3584);                   \
        const ulonglong2* t0 = (const ulonglong2*)&sm.th[(P)][0][kb * 32];         \
        const ulonglong2* t1 = (const ulonglong2*)&sm.th[(P)][1][kb * 32];         \
        unsigned long long a00 = 0ull, a01 = 0ull, a10 = 0ull, a11 = 0ull;         \
        _Pragma("unroll")                                                          \
        for (int i = 0; i < 8; i++) {                                              \
            ulonglong2 U = t0[i];                                                  \
            ulonglong2 V = t1[i];                                                  \
            a00 = ffma2(wp0[2*i],   U.x, a00);                                     \
            a00 = ffma2(wp0[2*i+1], U.y, a00);                                     \
            a01 = ffma2(wp1[2*i],   U.x, a01);                                     \
            a01 = ffma2(wp1[2*i+1], U.y, a01);                                     \
            a10 = ffma2(wp0[2*i],   V.x, a10);                                     \
            a10 = ffma2(wp0[2*i+1], V.y, a10);                                     \
            a11 = ffma2(wp1[2*i],   V.x, a11);                                     \
            a11 = ffma2(wp1[2*i+1], V.y, a11);                                     \
        }                                                                          \
        *(float2*)&sm.part[kb][j0]      = make_float2(fold2(a00), fold2(a01));     \
        *(float2*)&sm.part[kb][64 + j0] = make_float2(fold2(a10), fold2(a11));     \
        __syncthreads();                                                           \
        if (t < 128) {                                                             \
            float v0 = sm.part[0][t], v1 = sm.part[1][t];                          \
            float v2 = sm.part[2][t], v3 = sm.part[3][t];                          \
            _Pragma("unroll")                                                      \
            for (int w = 4; w < 16; w += 4) {                                      \
                v0 += sm.part[w][t];     v1 += sm.part[w + 1][t];                  \
                v2 += sm.part[w + 2][t]; v3 += sm.part[w + 3][t];                  \
            }                                                                      \
            float v = (v0 + v1) + (v2 + v3);                                       \
            h = fmaf(h, Acoef, fmaf(v, inv_tau, pre));                             \
            float thv = fast_tanh(h);                                              \
            float tho = __shfl_xor_sync(0xffffffffu, thv, 1);                      \
            float ho  = __shfl_xor_sync(0xffffffffu, h,   1);                      \
            if (!(t & 1))                                                          \
                *(float2*)(outp + (size_t)(STEP) * H_DIM) = make_float2(h, ho);    \
            if (!(LAST)) {                                                         \
                unsigned long long pk = (t & 1) ? pack2(tho, thv)                  \
                                                : pack2(thv, tho);                 \
                uint32_t d = (uint32_t)(((P) ^ 1) * 4096) + send_off;              \
                uint32_t m = mbar_rel + (((P) ^ 1) * 8u);                          \
                if (!(t & 1)) sts_b64(th_base + d, pk);                            \
                _Pragma("unroll")                                                  \
                for (int rr = 0; rr < 4; rr++) {                                   \
                    int pr = peer0 + rr;                                           \
                    if (pr != rank)                                                \
                        st_async_b64(peer_th[pr] + d, pk, peer_th[pr] + m);        \
                }                                                                  \
                if (!(t & 1))                                                      \
                    mbar_arrive_release(mbar_base + (((P) ^ 1) * 8u));             \
            }                                                                      \
            pre = fmaf(xn, inv_tau, c0);                                           \
        }                                                                          \
        (PH) ^= 1;                                                                 \
    }

    for (int s = 1; s < S_LEN - 1; s += 2) {
        STEP_BODY(s,     1, ph1, 0)
        STEP_BODY(s + 1, 0, ph0, 0)
    }
    STEP_BODY(S_LEN - 1, 1, ph1, 1)
#undef STEP_BODY

    cluster_sync();   // no CTA exits while peers' st.async may target its smem
}

extern "C" void kernel_launch(void* const* d_in, const int* in_sizes, int n_in,
                              void* d_out, int out_size)
{
    const float* x    = (const float*)d_in[0];
    const float* Wx   = (const float*)d_in[1];
    const float* Wh   = (const float*)d_in[2];
    const float* tau  = (const float*)d_in[3];
    const float* bias = (const float*)d_in[4];
    float* out = (float*)d_out;

    dim3 g1(H_DIM / BN, (B_SZ * S_LEN) / BM);
    xproj_kernel<<<g1, 256>>>(x, Wx, out);

    rec_kernel<<<NCLUSTERS * CRANKS, REC_THREADS>>>(Wh, tau, bias, out);
}

// round 15
// speedup vs baseline: 1.5101x; 1.0758x over previous
#include <cuda_runtime.h>
#include <cstdint>

#define S_LEN 2048
#define B_SZ  32
#define I_DIM 256
#define H_DIM 512

#define NCLUSTERS    16
#define CRANKS       8
#define ROWS_PER_CTA 64
#define REC_THREADS  512

// ---------------- PTX helpers ----------------
__device__ __forceinline__ uint32_t smem_u32(const void* p) {
    uint32_t a;
    asm("{ .reg .u64 t; cvta.to.shared.u64 t, %1; cvt.u32.u64 %0, t; }" : "=r"(a) : "l"(p));
    return a;
}
__device__ __forceinline__ uint32_t mapa_cluster(uint32_t addr, uint32_t rank) {
    uint32_t r;
    asm("mapa.shared::cluster.u32 %0, %1, %2;" : "=r"(r) : "r"(addr), "r"(rank));
    return r;
}
__device__ __forceinline__ void mbar_init(uint32_t mbar, uint32_t cnt) {
    asm volatile("mbarrier.init.shared.b64 [%0], %1;" :: "r"(mbar), "r"(cnt) : "memory");
}
__device__ __forceinline__ void mbar_expect_tx(uint32_t mbar, uint32_t bytes) {
    asm volatile("mbarrier.arrive.expect_tx.shared.b64 _, [%0], %1;" :: "r"(mbar), "r"(bytes) : "memory");
}
__device__ __forceinline__ void mbar_wait(uint32_t mbar, uint32_t phase) {
    uint32_t done = 0;
    while (!done) {
        asm volatile(
            "{\n\t.reg .pred p;\n\t"
            "mbarrier.try_wait.parity.acquire.cluster.shared::cta.b64 p, [%1], %2, 0x989680;\n\t"
            "selp.b32 %0, 1, 0, p;\n\t}"
            : "=r"(done) : "r"(mbar), "r"(phase) : "memory");
    }
}
__device__ __forceinline__ void st_async_b64(uint32_t daddr, unsigned long long v, uint32_t mbar) {
    asm volatile("st.async.shared::cluster.mbarrier::complete_tx::bytes.b64 [%0], %1, [%2];"
                 :: "r"(daddr), "l"(v), "r"(mbar) : "memory");
}
__device__ __forceinline__ unsigned long long ffma2(unsigned long long a, unsigned long long b,
                                                    unsigned long long c) {
    unsigned long long d;
    asm("fma.rn.f32x2 %0, %1, %2, %3;" : "=l"(d) : "l"(a), "l"(b), "l"(c));
    return d;
}
__device__ __forceinline__ float fold2(unsigned long long v) {
    union { unsigned long long u; float2 f; } c; c.u = v;
    return c.f.x + c.f.y;
}
__device__ __forceinline__ unsigned long long pack2(float x, float y) {
    unsigned long long r;
    asm("mov.b64 %0, {%1, %2};" : "=l"(r) : "r"(__float_as_uint(x)), "r"(__float_as_uint(y)));
    return r;
}
__device__ __forceinline__ float fast_tanh(float h) {
    float hc = fminf(fmaxf(h, -15.f), 15.f);
    float e2 = __expf(2.f * hc);
    return __fdividef(e2 - 1.f, e2 + 1.f);
}
__device__ __forceinline__ void cluster_sync() {
    asm volatile("barrier.cluster.arrive.aligned;\n\tbarrier.cluster.wait.aligned;" ::: "memory");
}

// ---------------- xproj GEMM (f32x2, validated R14): out[m,n] = sum_k x[m,k]*Wx[n,k] ----
#define BM 128
#define BN 128
#define BK 16

__global__ void __launch_bounds__(256, 2)
xproj_kernel(const float* __restrict__ x,
             const float* __restrict__ Wx,
             float* __restrict__ out)
{
    __shared__ float As[BK][BM];
    __shared__ float Bs[BK][BN];
    const int tid = threadIdx.x;
    const int m0 = blockIdx.y * BM;
    const int n0 = blockIdx.x * BN;
    const int tx = tid & 15;
    const int ty = tid >> 4;

    unsigned long long acc[8][4];   // [i][jpair], lo = col 2j, hi = col 2j+1
#pragma unroll
    for (int i = 0; i < 8; i++)
#pragma unroll
        for (int j = 0; j < 4; j++) acc[i][j] = 0ull;

    const float* Aptr = x  + (size_t)m0 * I_DIM;
    const float* Bptr = Wx + (size_t)n0 * I_DIM;

    for (int k0 = 0; k0 < I_DIM; k0 += BK) {
#pragma unroll
        for (int l = 0; l < 2; l++) {
            int idx = tid + l * 256;
            int r   = idx >> 2;
            int c4  = (idx & 3) * 4;
            float4 a = *(const float4*)(Aptr + (size_t)r * I_DIM + k0 + c4);
            As[c4 + 0][r] = a.x; As[c4 + 1][r] = a.y;
            As[c4 + 2][r] = a.z; As[c4 + 3][r] = a.w;
            float4 b = *(const float4*)(Bptr + (size_t)r * I_DIM + k0 + c4);
            Bs[c4 + 0][r] = b.x; Bs[c4 + 1][r] = b.y;
            Bs[c4 + 2][r] = b.z; Bs[c4 + 3][r] = b.w;
        }
        __syncthreads();
#pragma unroll
        for (int kk = 0; kk < BK; kk++) {
            float4 ra0 = *(const float4*)&As[kk][ty * 8];
            float4 ra1 = *(const float4*)&As[kk][ty * 8 + 4];
            float ra[8] = {ra0.x, ra0.y, ra0.z, ra0.w, ra1.x, ra1.y, ra1.z, ra1.w};
            const ulonglong2* rbp = (const ulonglong2*)&Bs[kk][tx * 8];
            ulonglong2 rb01 = rbp[0];
            ulonglong2 rb23 = rbp[1];
#pragma unroll
            for (int i = 0; i < 8; i++) {
                unsigned long long rai = pack2(ra[i], ra[i]);
                acc[i][0] = ffma2(rai, rb01.x, acc[i][0]);
                acc[i][1] = ffma2(rai, rb01.y, acc[i][1]);
                acc[i][2] = ffma2(rai, rb23.x, acc[i][2]);
                acc[i][3] = ffma2(rai, rb23.y, acc[i][3]);
            }
        }
        __syncthreads();
    }

#pragma unroll
    for (int i = 0; i < 8; i++) {
        float* o = out + (size_t)(m0 + ty * 8 + i) * H_DIM + n0 + tx * 8;
        union { unsigned long long u; float2 f; } c0, c1, c2, c3;
        c0.u = acc[i][0]; c1.u = acc[i][1]; c2.u = acc[i][2]; c3.u = acc[i][3];
        *(float4*)o       = make_float4(c0.f.x, c0.f.y, c1.f.x, c1.f.y);
        *(float4*)(o + 4) = make_float4(c2.f.x, c2.f.y, c3.f.x, c3.f.y);
    }
}

// ---------------- recurrence (R7 champion, byte-identical) ----------------
// 16 clusters x 8 CTAs; cluster c: batches (2c, 2c+1). CTA rank r: rows
// [r*64, r*64+64), Wh slice in registers (f32x2 pairs). Per step: mbar wait ->
// broadcast-LDS GEMV (warp kb covers k-chunk kb*32; rows 2jp,2jp+1; both
// batches) -> partials stored at part[kb][owner_tid] (conflict-free reads) ->
// __syncthreads -> tail t<128 reduces part[w][t], updates h, tanh -> shfl pair
// exchange -> even lane sends b64 to peers 0-3, odd lane to peers 4-7.
struct RecSmem {
    float th[2][2][H_DIM];     // [buf][batch][k]  8KB  (st.async dest)
    float part[16][128];       // partials, column = owner tid
    unsigned long long mbar[2];
};

__global__ void __cluster_dims__(CRANKS, 1, 1) __launch_bounds__(REC_THREADS, 1)
rec_kernel(const float* __restrict__ Wh,
           const float* __restrict__ tau,
           const float* __restrict__ bias,
           float* __restrict__ out)
{
    __shared__ __align__(16) RecSmem sm;

    const int cid  = blockIdx.x / CRANKS;
    const int rank = blockIdx.x % CRANKS;
    const int t    = threadIdx.x;
    const int jp   = t & 31;
    const int kb   = t >> 5;
    const int j0   = 2 * jp;

    // Wh slice in registers (rows j0, j0+1; k in [kb*32, kb*32+32))
    unsigned long long wp0[16], wp1[16];
    {
        const ulonglong2* r0 = (const ulonglong2*)(Wh + (size_t)(rank * ROWS_PER_CTA + j0)     * H_DIM + kb * 32);
        const ulonglong2* r1 = (const ulonglong2*)(Wh + (size_t)(rank * ROWS_PER_CTA + j0 + 1) * H_DIM + kb * 32);
#pragma unroll
        for (int i = 0; i < 8; i++) {
            ulonglong2 a = r0[i]; wp0[2*i] = a.x; wp0[2*i+1] = a.y;
            ulonglong2 b = r1[i]; wp1[2*i] = b.x; wp1[2*i+1] = b.y;
        }
    }

    const uint32_t th_base   = smem_u32(&sm.th[0][0][0]);
    const uint32_t mbar_base = smem_u32(&sm.mbar[0]);
    const uint32_t mbar_rel  = mbar_base - th_base;

    uint32_t peer_th[CRANKS];
#pragma unroll
    for (int r = 0; r < CRANKS; r++) peer_th[r] = mapa_cluster(th_base, r);

    if (t == 0) {
        mbar_init(mbar_base,     1);  mbar_expect_tx(mbar_base,     4096);
        mbar_init(mbar_base + 8, 1);  mbar_expect_tx(mbar_base + 8, 4096);
    }
    __syncthreads();
    cluster_sync();   // peers' mbars live before any st.async

    // tail state (t < 128): one (batch, row) output per thread
    const int bb = t >> 6;
    const int j  = t & 63;
    const int hg = rank * ROWS_PER_CTA + j;
    const int b  = cid * 2 + bb;
    float* outp = out + (size_t)b * S_LEN * H_DIM + hg;

    float h = 0.f, inv_tau = 1.f, bias_r = 0.f, xc = 0.f;
    if (t < 128) {
        inv_tau = 1.0f / tau[hg];
        bias_r  = bias[hg];
    }
    // b64 destination offset: even-row base of this thread's pair
    const uint32_t send_off = (uint32_t)(bb * H_DIM + (hg & ~1)) * 4u;
    const int peer0 = (t & 1) * 4;   // even lane: peers 0-3, odd: peers 4-7

    // ---- step 0: v = 0 ----
    if (t < 128) {
        xc = outp[0];
        h = (xc + bias_r) * inv_tau;
        float thv = fast_tanh(h);
        float tho = __shfl_xor_sync(0xffffffffu, thv, 1);
        float ho  = __shfl_xor_sync(0xffffffffu, h,   1);
        if (!(t & 1)) *(float2*)outp = make_float2(h, ho);
        unsigned long long pk = (t & 1) ? pack2(tho, thv) : pack2(thv, tho);
        uint32_t d = (uint32_t)(2 * H_DIM * 4) + send_off;    // parity-1 buffer
        uint32_t m = mbar_rel + 8u;
#pragma unroll
        for (int rr = 0; rr < 4; rr++)
            st_async_b64(peer_th[peer0 + rr] + d, pk, peer_th[peer0 + rr] + m);
        xc = outp[(size_t)1 * H_DIM];                         // prefetch step 1
    }

    uint32_t ph0 = 0, ph1 = 0;

#define STEP_BODY(STEP, P, PH, LAST)                                               \
    {                                                                              \
        float xn = 0.f;                                                            \
        if (t < 128 && !(LAST)) xn = outp[(size_t)((STEP) + 1) * H_DIM];           \
        mbar_wait(mbar_base + (P) * 8, (PH));                                      \
        if (t == 0) mbar_expect_tx(mbar_base + (P) * 8, 4096);                     \
        const ulonglong2* t0 = (const ulonglong2*)&sm.th[(P)][0][kb * 32];         \
        const ulonglong2* t1 = (const ulonglong2*)&sm.th[(P)][1][kb * 32];         \
        unsigned long long a00 = 0ull, a01 = 0ull, a10 = 0ull, a11 = 0ull;         \
        _Pragma("unroll")                                                          \
        for (int i = 0; i < 8; i++) {                                              \
            ulonglong2 U = t0[i];                                                  \
            ulonglong2 V = t1[i];                                                  \
            a00 = ffma2(wp0[2*i],   U.x, a00);                                     \
            a00 = ffma2(wp0[2*i+1], U.y, a00);                                     \
            a01 = ffma2(wp1[2*i],   U.x, a01);                                     \
            a01 = ffma2(wp1[2*i+1], U.y, a01);                                     \
            a10 = ffma2(wp0[2*i],   V.x, a10);                                     \
            a10 = ffma2(wp0[2*i+1], V.y, a10);                                     \
            a11 = ffma2(wp1[2*i],   V.x, a11);                                     \
            a11 = ffma2(wp1[2*i+1], V.y, a11);                                     \
        }                                                                          \
        *(float2*)&sm.part[kb][j0]      = make_float2(fold2(a00), fold2(a01));     \
        *(float2*)&sm.part[kb][64 + j0] = make_float2(fold2(a10), fold2(a11));     \
        __syncthreads();                                                           \
        if (t < 128) {                                                             \
            float v = 0.f;                                                         \
            _Pragma("unroll")                                                      \
            for (int w = 0; w < 16; w++) v += sm.part[w][t];                       \
            h = h + (xc - h + v + bias_r) * inv_tau;                               \
            float thv = fast_tanh(h);                                              \
            float tho = __shfl_xor_sync(0xffffffffu, thv, 1);                      \
            float ho  = __shfl_xor_sync(0xffffffffu, h,   1);                      \
            if (!(t & 1))                                                          \
                *(float2*)(outp + (size_t)(STEP) * H_DIM) = make_float2(h, ho);    \
            if (!(LAST)) {                                                         \
                unsigned long long pk = (t & 1) ? pack2(tho, thv)                  \
                                                : pack2(thv, tho);                 \
                uint32_t d = (uint32_t)(((P) ^ 1) * 2 * H_DIM * 4) + send_off;     \
                uint32_t m = mbar_rel + (((P) ^ 1) * 8u);                          \
                _Pragma("unroll")                                                  \
                for (int rr = 0; rr < 4; rr++)                                     \
                    st_async_b64(peer_th[peer0 + rr] + d, pk,                      \
                                 peer_th[peer0 + rr] + m);                         \
            }                                                                      \
        }                                                                          \
        xc = xn;                                                                   \
        (PH) ^= 1;                                                                 \
    }

    for (int s = 1; s < S_LEN - 1; s += 2) {
        STEP_BODY(s,     1, ph1, 0)
        STEP_BODY(s + 1, 0, ph0, 0)
    }
    STEP_BODY(S_LEN - 1, 1, ph1, 1)
#undef STEP_BODY

    cluster_sync();   // no CTA exits while peers' st.async may target its smem
}

extern "C" void kernel_launch(void* const* d_in, const int* in_sizes, int n_in,
                              void* d_out, int out_size)
{
    const float* x    = (const float*)d_in[0];
    const float* Wx   = (const float*)d_in[1];
    const float* Wh   = (const float*)d_in[2];
    const float* tau  = (const float*)d_in[3];
    const float* bias = (const float*)d_in[4];
    float* out = (float*)d_out;

    dim3 g1(H_DIM / BN, (B_SZ * S_LEN) / BM);
    xproj_kernel<<<g1, 256>>>(x, Wx, out);

    rec_kernel<<<NCLUSTERS * CRANKS, REC_THREADS>>>(Wh, tau, bias, out);
}